// round 12
// baseline (speedup 1.0000x reference)
#include <cuda_runtime.h>
#include <stdint.h>

// ---------------------------------------------------------------------------
// LoraSubnet: exact top-10% mask of |scores| with stable-sort tie-break by
// flat index, two independent 16,777,216-element fp32 matrices.
//
// 3-kernel pipeline (graph-capturable, scratch in __device__ globals):
//   K1 sample : 8192-bin histogram of absbits[30:18] over the first n/16
//               elements (8 MB read); last block selects the prefix bin at
//               sampled rank j/16 and sets a 4-bin bracket [L, L+2^20) in bit
//               space (>27-sigma safety for iid uniform data); zeroes the
//               sample hist for the next replay.
//   K2 bracket: full 128 MB read; per-thread register count of bits < L
//               (block-reduced, one global atomic per block) + fine 2^20-bin
//               and coarse 4096-bin histograms of in-bracket elements (spread
//               global atomics, ~1M/matrix); last block computes
//               j_rem = j - count_below and 2-level rank-selects -> exact
//               T32 + tie rank r.
//   K3 mask   : out = (bits > T32); appends indices with bits == T32 to a
//               tiny tie list; zeroes fine/coarse hists; last block per
//               matrix resolves ties in-place (out[idx]=1 for rank >= r).
// ---------------------------------------------------------------------------

#define H1_BITS 13
#define H1_BINS (1 << H1_BITS)     // 8192
#define H2_BITS 18                 // low bits per prefix bin
#define SBITS 4                    // sample fraction = 1/16
#define BRK 4                      // bracket width in prefix bins
#define FINE_BINS (BRK << H2_BITS) // 2^20
#define FINE_SPAN ((unsigned)FINE_BINS)
#define CRS_BINS (FINE_BINS >> 8)  // 4096
#define ABS_MASK 0x7fffffffu
#define TIE_CAP 16384

#define G1X 74
#define G1T 256
#define G2X 1184
#define G2T 256
#define GMX 1184
#define GMT 256

struct SelState {
    unsigned L;    // bracket base in abs-bit space (lo_prefix << 18)
    unsigned T32;  // exact abs-bits threshold (bits of rank-j element)
    unsigned r;    // tie rank: r smallest-index ties are zeroed
};

__device__ unsigned g_shist[2][H1_BINS];
__device__ unsigned g_fine[2][FINE_BINS];
__device__ unsigned g_crs[2][CRS_BINS];
__device__ unsigned g_below[2];
__device__ unsigned g_tie_idx[2][TIE_CAP];
__device__ unsigned g_tie_cnt[2];
__device__ unsigned g_done1[2];
__device__ unsigned g_done2[2];
__device__ unsigned g_done3[2];
__device__ SelState g_state[2];

// ---------------------------------------------------------------------------
// K1: sampled 13-bit histogram + bracket selection (last block per matrix)
// ---------------------------------------------------------------------------
__global__ __launch_bounds__(G1T) void sample_kernel(
    const float4* __restrict__ A, const float4* __restrict__ B,
    int n4, unsigned j) {
    __shared__ unsigned sh[H1_BINS];
    const int m = blockIdx.y;
    const float4* src = m ? B : A;
    const int ns4 = n4 >> SBITS;  // first 1/16 of the array

    for (int i = threadIdx.x; i < H1_BINS; i += G1T) sh[i] = 0;
    __syncthreads();

    const int stride = G1T * gridDim.x;
    for (int i = blockIdx.x * G1T + threadIdx.x; i < ns4; i += stride) {
        float4 v = __ldg(src + i);
        atomicAdd(&sh[(__float_as_uint(v.x) & ABS_MASK) >> H2_BITS], 1u);
        atomicAdd(&sh[(__float_as_uint(v.y) & ABS_MASK) >> H2_BITS], 1u);
        atomicAdd(&sh[(__float_as_uint(v.z) & ABS_MASK) >> H2_BITS], 1u);
        atomicAdd(&sh[(__float_as_uint(v.w) & ABS_MASK) >> H2_BITS], 1u);
    }
    __syncthreads();

    unsigned* gh = g_shist[m];
    for (int k = threadIdx.x; k < H1_BINS; k += G1T) {
        unsigned c = sh[k];
        if (c) atomicAdd(&gh[k], c);
    }

    // ---- last-block-done handshake ----
    __threadfence();
    __syncthreads();
    __shared__ unsigned s_isLast;
    if (threadIdx.x == 0)
        s_isLast = (atomicAdd(&g_done1[m], 1u) == gridDim.x - 1u) ? 1u : 0u;
    __syncthreads();
    if (!s_isLast) return;
    __threadfence();

    // ---- select sampled rank j/16 over 8192 bins (32 per thread) ----
    const unsigned js = j >> SBITS;
    constexpr int PER = H1_BINS / G1T;  // 32
    unsigned bins[PER];
    unsigned local = 0;
    const int base = threadIdx.x * PER;
#pragma unroll
    for (int q = 0; q < PER; q++) {
        bins[q] = gh[base + q];
        local += bins[q];
    }
    __shared__ unsigned s_scan[G1T];
    s_scan[threadIdx.x] = local;
    __syncthreads();
    for (int off = 1; off < G1T; off <<= 1) {
        unsigned t = (threadIdx.x >= off) ? s_scan[threadIdx.x - off] : 0u;
        __syncthreads();
        s_scan[threadIdx.x] += t;
        __syncthreads();
    }
    const unsigned incl = s_scan[threadIdx.x];
    const unsigned excl = incl - local;
    if (js >= excl && js < incl) {
        unsigned acc = excl;
        unsigned p_est = (unsigned)base;
#pragma unroll
        for (int q = 0; q < PER; q++) {
            if (js < acc + bins[q]) { p_est = (unsigned)(base + q); break; }
            acc += bins[q];
        }
        unsigned lo = (p_est >= 1u) ? p_est - 1u : 0u;
        if (lo > (unsigned)(H1_BINS - BRK)) lo = (unsigned)(H1_BINS - BRK);
        g_state[m].L = lo << H2_BITS;
    }
    __syncthreads();
    // zero sample hist for next replay; reset done counter
    for (int k = threadIdx.x; k < H1_BINS; k += G1T) gh[k] = 0;
    if (threadIdx.x == 0) g_done1[m] = 0;
}

// ---------------------------------------------------------------------------
// K2: full pass — count below bracket + fine/coarse bracket histogram +
//     fused exact 2-level rank-select (last block per matrix)
// ---------------------------------------------------------------------------
__global__ __launch_bounds__(G2T) void bracket_kernel(
    const float4* __restrict__ A, const float4* __restrict__ B,
    int n4, unsigned j) {
    const int m = blockIdx.y;
    const float4* src = m ? B : A;
    const unsigned L = g_state[m].L;
    unsigned* fine = g_fine[m];
    unsigned* crs = g_crs[m];

    unsigned below = 0;
    const int stride = G2T * gridDim.x;
    int i = blockIdx.x * G2T + threadIdx.x;
    for (; i + stride < n4; i += 2 * stride) {
        float4 v0 = __ldg(src + i);
        float4 v1 = __ldg(src + i + stride);
        unsigned b, f;
        b = __float_as_uint(v0.x) & ABS_MASK; below += (b < L);
        f = b - L; if (f < FINE_SPAN) { atomicAdd(&fine[f], 1u); atomicAdd(&crs[f >> 8], 1u); }
        b = __float_as_uint(v0.y) & ABS_MASK; below += (b < L);
        f = b - L; if (f < FINE_SPAN) { atomicAdd(&fine[f], 1u); atomicAdd(&crs[f >> 8], 1u); }
        b = __float_as_uint(v0.z) & ABS_MASK; below += (b < L);
        f = b - L; if (f < FINE_SPAN) { atomicAdd(&fine[f], 1u); atomicAdd(&crs[f >> 8], 1u); }
        b = __float_as_uint(v0.w) & ABS_MASK; below += (b < L);
        f = b - L; if (f < FINE_SPAN) { atomicAdd(&fine[f], 1u); atomicAdd(&crs[f >> 8], 1u); }
        b = __float_as_uint(v1.x) & ABS_MASK; below += (b < L);
        f = b - L; if (f < FINE_SPAN) { atomicAdd(&fine[f], 1u); atomicAdd(&crs[f >> 8], 1u); }
        b = __float_as_uint(v1.y) & ABS_MASK; below += (b < L);
        f = b - L; if (f < FINE_SPAN) { atomicAdd(&fine[f], 1u); atomicAdd(&crs[f >> 8], 1u); }
        b = __float_as_uint(v1.z) & ABS_MASK; below += (b < L);
        f = b - L; if (f < FINE_SPAN) { atomicAdd(&fine[f], 1u); atomicAdd(&crs[f >> 8], 1u); }
        b = __float_as_uint(v1.w) & ABS_MASK; below += (b < L);
        f = b - L; if (f < FINE_SPAN) { atomicAdd(&fine[f], 1u); atomicAdd(&crs[f >> 8], 1u); }
    }
    if (i < n4) {
        float4 v = __ldg(src + i);
        unsigned b, f;
        b = __float_as_uint(v.x) & ABS_MASK; below += (b < L);
        f = b - L; if (f < FINE_SPAN) { atomicAdd(&fine[f], 1u); atomicAdd(&crs[f >> 8], 1u); }
        b = __float_as_uint(v.y) & ABS_MASK; below += (b < L);
        f = b - L; if (f < FINE_SPAN) { atomicAdd(&fine[f], 1u); atomicAdd(&crs[f >> 8], 1u); }
        b = __float_as_uint(v.z) & ABS_MASK; below += (b < L);
        f = b - L; if (f < FINE_SPAN) { atomicAdd(&fine[f], 1u); atomicAdd(&crs[f >> 8], 1u); }
        b = __float_as_uint(v.w) & ABS_MASK; below += (b < L);
        f = b - L; if (f < FINE_SPAN) { atomicAdd(&fine[f], 1u); atomicAdd(&crs[f >> 8], 1u); }
    }

    // block-reduce `below`, one global atomic per block
    __shared__ unsigned s_red[G2T];
    s_red[threadIdx.x] = below;
    __syncthreads();
    for (int off = G2T / 2; off > 0; off >>= 1) {
        if (threadIdx.x < off) s_red[threadIdx.x] += s_red[threadIdx.x + off];
        __syncthreads();
    }
    if (threadIdx.x == 0) atomicAdd(&g_below[m], s_red[0]);

    // ---- last-block-done handshake ----
    __threadfence();
    __syncthreads();
    __shared__ unsigned s_isLast;
    if (threadIdx.x == 0)
        s_isLast = (atomicAdd(&g_done2[m], 1u) == gridDim.x - 1u) ? 1u : 0u;
    __syncthreads();
    if (!s_isLast) return;
    __threadfence();

    const unsigned jrem = j - g_below[m];
    const int tid = threadIdx.x;
    __shared__ unsigned s_scan2[G2T];
    __shared__ unsigned s_cb, s_remc;

    // ---- level 1: 4096 coarse bins, 16 per thread (4x uint4) ----
    {
        const uint4* c4 = (const uint4*)crs;
        unsigned cb_[16];
        unsigned local = 0;
        const int b4 = tid * 4;
#pragma unroll
        for (int q = 0; q < 4; q++) {
            uint4 v = c4[b4 + q];
            cb_[q * 4 + 0] = v.x; cb_[q * 4 + 1] = v.y;
            cb_[q * 4 + 2] = v.z; cb_[q * 4 + 3] = v.w;
            local += v.x + v.y + v.z + v.w;
        }
        s_scan2[tid] = local;
        __syncthreads();
        for (int off = 1; off < G2T; off <<= 1) {
            unsigned t = (tid >= off) ? s_scan2[tid - off] : 0u;
            __syncthreads();
            s_scan2[tid] += t;
            __syncthreads();
        }
        const unsigned incl = s_scan2[tid];
        const unsigned excl = incl - local;
        if (jrem >= excl && jrem < incl) {
            unsigned acc = excl;
#pragma unroll
            for (int q = 0; q < 16; q++) {
                if (jrem < acc + cb_[q]) {
                    s_cb = (unsigned)(tid * 16 + q);
                    s_remc = jrem - acc;
                    break;
                }
                acc += cb_[q];
            }
        }
        __syncthreads();
    }
    const unsigned cb = s_cb;
    const unsigned remc = s_remc;
    __syncthreads();

    // ---- level 2: 256 fine bins of coarse bucket cb ----
    {
        unsigned local = fine[cb * 256u + (unsigned)tid];
        s_scan2[tid] = local;
        __syncthreads();
        for (int off = 1; off < G2T; off <<= 1) {
            unsigned t = (tid >= off) ? s_scan2[tid - off] : 0u;
            __syncthreads();
            s_scan2[tid] += t;
            __syncthreads();
        }
        const unsigned incl = s_scan2[tid];
        const unsigned excl = incl - local;
        if (remc >= excl && remc < incl) {
            g_state[m].T32 = L + cb * 256u + (unsigned)tid;
            g_state[m].r = remc - excl;
        }
    }
    if (threadIdx.x == 0) {
        g_below[m] = 0;  // reset for next replay
        g_done2[m] = 0;
    }
}

// ---------------------------------------------------------------------------
// K3: mask write (strict >) + tie collection + hist zeroing + fused tie fix
// ---------------------------------------------------------------------------
__global__ __launch_bounds__(GMT) void mask_kernel(
    const float4* __restrict__ A, const float4* __restrict__ B,
    float4* __restrict__ out, int n4) {
    const int m = blockIdx.y;
    const float4* src = m ? B : A;
    float4* dst = out + (size_t)m * (size_t)n4;
    const unsigned T = g_state[m].T32;

    const int stride = GMT * gridDim.x;
    for (int i = blockIdx.x * GMT + threadIdx.x; i < n4; i += stride) {
        float4 v = __ldg(src + i);
        unsigned bx = __float_as_uint(v.x) & ABS_MASK;
        unsigned by = __float_as_uint(v.y) & ABS_MASK;
        unsigned bz = __float_as_uint(v.z) & ABS_MASK;
        unsigned bw = __float_as_uint(v.w) & ABS_MASK;
        float4 o;
        o.x = (bx > T) ? 1.0f : 0.0f;
        o.y = (by > T) ? 1.0f : 0.0f;
        o.z = (bz > T) ? 1.0f : 0.0f;
        o.w = (bw > T) ? 1.0f : 0.0f;
        dst[i] = o;
        // exact-equality ties are extremely sparse (~1-16 per matrix)
        if (bx == T || by == T || bz == T || bw == T) {
            const unsigned idx = 4u * (unsigned)i;
            if (bx == T) {
                unsigned p = atomicAdd(&g_tie_cnt[m], 1u);
                if (p < TIE_CAP) g_tie_idx[m][p] = idx + 0u;
            }
            if (by == T) {
                unsigned p = atomicAdd(&g_tie_cnt[m], 1u);
                if (p < TIE_CAP) g_tie_idx[m][p] = idx + 1u;
            }
            if (bz == T) {
                unsigned p = atomicAdd(&g_tie_cnt[m], 1u);
                if (p < TIE_CAP) g_tie_idx[m][p] = idx + 2u;
            }
            if (bw == T) {
                unsigned p = atomicAdd(&g_tie_cnt[m], 1u);
                if (p < TIE_CAP) g_tie_idx[m][p] = idx + 3u;
            }
        }
    }

    // zero bracket histograms for the next graph replay
    {
        const int tid = ((int)blockIdx.y * (int)gridDim.x + (int)blockIdx.x) * GMT
                        + (int)threadIdx.x;
        const int tot = (int)gridDim.x * 2 * GMT;
        uint4 z4 = make_uint4(0u, 0u, 0u, 0u);
        uint4* f4 = (uint4*)&g_fine[0][0];
        for (int k = tid; k < 2 * FINE_BINS / 4; k += tot) f4[k] = z4;
        unsigned* cc = &g_crs[0][0];
        for (int k = tid; k < 2 * CRS_BINS; k += tot) cc[k] = 0;
    }

    // ---- last-block-done handshake, then in-place tie resolution ----
    __threadfence();
    __syncthreads();
    __shared__ unsigned s_isLast;
    if (threadIdx.x == 0)
        s_isLast = (atomicAdd(&g_done3[m], 1u) == gridDim.x - 1u) ? 1u : 0u;
    __syncthreads();
    if (!s_isLast) return;
    __threadfence();

    unsigned tc = g_tie_cnt[m];
    if (tc > TIE_CAP) tc = TIE_CAP;
    const unsigned r = g_state[m].r;
    float* dstf = (float*)(out) + (size_t)m * (size_t)n4 * 4u;
    for (unsigned e = threadIdx.x; e < tc; e += GMT) {
        const unsigned my = g_tie_idx[m][e];
        unsigned rk = 0;
        for (unsigned k = 0; k < tc; k++)
            rk += (g_tie_idx[m][k] < my) ? 1u : 0u;
        if (rk >= r) dstf[my] = 1.0f;
    }
    __syncthreads();
    if (threadIdx.x == 0) {
        g_tie_cnt[m] = 0;  // reset for next replay
        g_done3[m] = 0;
    }
}

// ---------------------------------------------------------------------------
extern "C" void kernel_launch(void* const* d_in, const int* in_sizes, int n_in,
                              void* d_out, int out_size) {
    const float4* A = (const float4*)d_in[0];
    const float4* B = (const float4*)d_in[1];
    float4* out = (float4*)d_out;

    const unsigned n = (unsigned)in_sizes[0];  // 16,777,216 per matrix
    const int n4 = (int)(n / 4u);
    // Mirror Python int((1.0 - 0.1) * n) exactly (double arithmetic, truncate)
    const unsigned j = (unsigned)((1.0 - 0.1) * (double)n);

    dim3 g1(G1X, 2);
    sample_kernel<<<g1, G1T>>>(A, B, n4, j);

    dim3 g2(G2X, 2);
    bracket_kernel<<<g2, G2T>>>(A, B, n4, j);

    dim3 gm(GMX, 2);
    mask_kernel<<<gm, GMT>>>(A, B, out, n4);
}

// round 13
// speedup vs baseline: 1.0134x; 1.0134x over previous
#include <cuda_runtime.h>
#include <stdint.h>

// ---------------------------------------------------------------------------
// LoraSubnet: exact top-10% mask of |scores| with stable-sort tie-break by
// flat index, two independent 16,777,216-element fp32 matrices.
//
// 3-kernel pipeline (graph-capturable, scratch in __device__ globals):
//   K1 sample : 8192-bin histogram of absbits[30:18] over the first n/16
//               elements (8 MB read); last block selects the prefix bin at
//               sampled rank j/16 and sets a 4-bin bracket [L, L+2^20) in bit
//               space (>27-sigma safety for iid uniform data); zeroes the
//               sample hist for the next replay.
//   K2 bracket: full 128 MB read; per-thread register count of bits < L
//               (block-reduced, one global atomic per block) + fine 2^20-bin
//               and coarse 4096-bin histograms of in-bracket elements (spread
//               global atomics, ~1M/matrix); last block computes
//               j_rem = j - count_below and 2-level rank-selects -> exact
//               T32 + tie rank r.
//   K3 mask   : out = (bits > T32); appends indices with bits == T32 to a
//               tiny tie list; zeroes fine/coarse hists; last block per
//               matrix resolves ties in-place (out[idx]=1 for rank >= r).
// ---------------------------------------------------------------------------

#define H1_BITS 13
#define H1_BINS (1 << H1_BITS)     // 8192
#define H2_BITS 18                 // low bits per prefix bin
#define SBITS 4                    // sample fraction = 1/16
#define BRK 4                      // bracket width in prefix bins
#define FINE_BINS (BRK << H2_BITS) // 2^20
#define FINE_SPAN ((unsigned)FINE_BINS)
#define CRS_BINS (FINE_BINS >> 8)  // 4096
#define ABS_MASK 0x7fffffffu
#define TIE_CAP 16384

#define G1X 74
#define G1T 256
#define G2X 1184
#define G2T 256
#define GMX 1184
#define GMT 256

struct SelState {
    unsigned L;    // bracket base in abs-bit space (lo_prefix << 18)
    unsigned T32;  // exact abs-bits threshold (bits of rank-j element)
    unsigned r;    // tie rank: r smallest-index ties are zeroed
};

__device__ unsigned g_shist[2][H1_BINS];
__device__ unsigned g_fine[2][FINE_BINS];
__device__ unsigned g_crs[2][CRS_BINS];
__device__ unsigned g_below[2];
__device__ unsigned g_tie_idx[2][TIE_CAP];
__device__ unsigned g_tie_cnt[2];
__device__ unsigned g_done1[2];
__device__ unsigned g_done2[2];
__device__ unsigned g_done3[2];
__device__ SelState g_state[2];

// ---------------------------------------------------------------------------
// K1: sampled 13-bit histogram + bracket selection (last block per matrix)
// ---------------------------------------------------------------------------
__global__ __launch_bounds__(G1T) void sample_kernel(
    const float4* __restrict__ A, const float4* __restrict__ B,
    int n4, unsigned j) {
    __shared__ unsigned sh[H1_BINS];
    const int m = blockIdx.y;
    const float4* src = m ? B : A;
    const int ns4 = n4 >> SBITS;  // first 1/16 of the array

    for (int i = threadIdx.x; i < H1_BINS; i += G1T) sh[i] = 0;
    __syncthreads();

    const int stride = G1T * gridDim.x;
    for (int i = blockIdx.x * G1T + threadIdx.x; i < ns4; i += stride) {
        float4 v = __ldg(src + i);
        atomicAdd(&sh[(__float_as_uint(v.x) & ABS_MASK) >> H2_BITS], 1u);
        atomicAdd(&sh[(__float_as_uint(v.y) & ABS_MASK) >> H2_BITS], 1u);
        atomicAdd(&sh[(__float_as_uint(v.z) & ABS_MASK) >> H2_BITS], 1u);
        atomicAdd(&sh[(__float_as_uint(v.w) & ABS_MASK) >> H2_BITS], 1u);
    }
    __syncthreads();

    unsigned* gh = g_shist[m];
    for (int k = threadIdx.x; k < H1_BINS; k += G1T) {
        unsigned c = sh[k];
        if (c) atomicAdd(&gh[k], c);
    }

    // ---- last-block-done handshake ----
    __threadfence();
    __syncthreads();
    __shared__ unsigned s_isLast;
    if (threadIdx.x == 0)
        s_isLast = (atomicAdd(&g_done1[m], 1u) == gridDim.x - 1u) ? 1u : 0u;
    __syncthreads();
    if (!s_isLast) return;
    __threadfence();

    // ---- select sampled rank j/16 over 8192 bins (32 per thread) ----
    const unsigned js = j >> SBITS;
    constexpr int PER = H1_BINS / G1T;  // 32
    unsigned bins[PER];
    unsigned local = 0;
    const int base = threadIdx.x * PER;
#pragma unroll
    for (int q = 0; q < PER; q++) {
        bins[q] = gh[base + q];
        local += bins[q];
    }
    __shared__ unsigned s_scan[G1T];
    s_scan[threadIdx.x] = local;
    __syncthreads();
    for (int off = 1; off < G1T; off <<= 1) {
        unsigned t = (threadIdx.x >= off) ? s_scan[threadIdx.x - off] : 0u;
        __syncthreads();
        s_scan[threadIdx.x] += t;
        __syncthreads();
    }
    const unsigned incl = s_scan[threadIdx.x];
    const unsigned excl = incl - local;
    if (js >= excl && js < incl) {
        unsigned acc = excl;
        unsigned p_est = (unsigned)base;
#pragma unroll
        for (int q = 0; q < PER; q++) {
            if (js < acc + bins[q]) { p_est = (unsigned)(base + q); break; }
            acc += bins[q];
        }
        unsigned lo = (p_est >= 1u) ? p_est - 1u : 0u;
        if (lo > (unsigned)(H1_BINS - BRK)) lo = (unsigned)(H1_BINS - BRK);
        g_state[m].L = lo << H2_BITS;
    }
    __syncthreads();
    // zero sample hist for next replay; reset done counter
    for (int k = threadIdx.x; k < H1_BINS; k += G1T) gh[k] = 0;
    if (threadIdx.x == 0) g_done1[m] = 0;
}

// ---------------------------------------------------------------------------
// K2: full pass — count below bracket + fine/coarse bracket histogram +
//     fused exact 2-level rank-select (last block per matrix)
// ---------------------------------------------------------------------------
__global__ __launch_bounds__(G2T) void bracket_kernel(
    const float4* __restrict__ A, const float4* __restrict__ B,
    int n4, unsigned j) {
    const int m = blockIdx.y;
    const float4* src = m ? B : A;
    const unsigned L = g_state[m].L;
    unsigned* fine = g_fine[m];
    unsigned* crs = g_crs[m];

    unsigned below = 0;
    const int stride = G2T * gridDim.x;
    int i = blockIdx.x * G2T + threadIdx.x;
    for (; i + stride < n4; i += 2 * stride) {
        float4 v0 = __ldg(src + i);
        float4 v1 = __ldg(src + i + stride);
        unsigned b, f;
        b = __float_as_uint(v0.x) & ABS_MASK; below += (b < L);
        f = b - L; if (f < FINE_SPAN) { atomicAdd(&fine[f], 1u); atomicAdd(&crs[f >> 8], 1u); }
        b = __float_as_uint(v0.y) & ABS_MASK; below += (b < L);
        f = b - L; if (f < FINE_SPAN) { atomicAdd(&fine[f], 1u); atomicAdd(&crs[f >> 8], 1u); }
        b = __float_as_uint(v0.z) & ABS_MASK; below += (b < L);
        f = b - L; if (f < FINE_SPAN) { atomicAdd(&fine[f], 1u); atomicAdd(&crs[f >> 8], 1u); }
        b = __float_as_uint(v0.w) & ABS_MASK; below += (b < L);
        f = b - L; if (f < FINE_SPAN) { atomicAdd(&fine[f], 1u); atomicAdd(&crs[f >> 8], 1u); }
        b = __float_as_uint(v1.x) & ABS_MASK; below += (b < L);
        f = b - L; if (f < FINE_SPAN) { atomicAdd(&fine[f], 1u); atomicAdd(&crs[f >> 8], 1u); }
        b = __float_as_uint(v1.y) & ABS_MASK; below += (b < L);
        f = b - L; if (f < FINE_SPAN) { atomicAdd(&fine[f], 1u); atomicAdd(&crs[f >> 8], 1u); }
        b = __float_as_uint(v1.z) & ABS_MASK; below += (b < L);
        f = b - L; if (f < FINE_SPAN) { atomicAdd(&fine[f], 1u); atomicAdd(&crs[f >> 8], 1u); }
        b = __float_as_uint(v1.w) & ABS_MASK; below += (b < L);
        f = b - L; if (f < FINE_SPAN) { atomicAdd(&fine[f], 1u); atomicAdd(&crs[f >> 8], 1u); }
    }
    if (i < n4) {
        float4 v = __ldg(src + i);
        unsigned b, f;
        b = __float_as_uint(v.x) & ABS_MASK; below += (b < L);
        f = b - L; if (f < FINE_SPAN) { atomicAdd(&fine[f], 1u); atomicAdd(&crs[f >> 8], 1u); }
        b = __float_as_uint(v.y) & ABS_MASK; below += (b < L);
        f = b - L; if (f < FINE_SPAN) { atomicAdd(&fine[f], 1u); atomicAdd(&crs[f >> 8], 1u); }
        b = __float_as_uint(v.z) & ABS_MASK; below += (b < L);
        f = b - L; if (f < FINE_SPAN) { atomicAdd(&fine[f], 1u); atomicAdd(&crs[f >> 8], 1u); }
        b = __float_as_uint(v.w) & ABS_MASK; below += (b < L);
        f = b - L; if (f < FINE_SPAN) { atomicAdd(&fine[f], 1u); atomicAdd(&crs[f >> 8], 1u); }
    }

    // block-reduce `below`, one global atomic per block
    __shared__ unsigned s_red[G2T];
    s_red[threadIdx.x] = below;
    __syncthreads();
    for (int off = G2T / 2; off > 0; off >>= 1) {
        if (threadIdx.x < off) s_red[threadIdx.x] += s_red[threadIdx.x + off];
        __syncthreads();
    }
    if (threadIdx.x == 0) atomicAdd(&g_below[m], s_red[0]);

    // ---- last-block-done handshake ----
    __threadfence();
    __syncthreads();
    __shared__ unsigned s_isLast;
    if (threadIdx.x == 0)
        s_isLast = (atomicAdd(&g_done2[m], 1u) == gridDim.x - 1u) ? 1u : 0u;
    __syncthreads();
    if (!s_isLast) return;
    __threadfence();

    const unsigned jrem = j - g_below[m];
    const int tid = threadIdx.x;
    __shared__ unsigned s_scan2[G2T];
    __shared__ unsigned s_cb, s_remc;

    // ---- level 1: 4096 coarse bins, 16 per thread (4x uint4) ----
    {
        const uint4* c4 = (const uint4*)crs;
        unsigned cb_[16];
        unsigned local = 0;
        const int b4 = tid * 4;
#pragma unroll
        for (int q = 0; q < 4; q++) {
            uint4 v = c4[b4 + q];
            cb_[q * 4 + 0] = v.x; cb_[q * 4 + 1] = v.y;
            cb_[q * 4 + 2] = v.z; cb_[q * 4 + 3] = v.w;
            local += v.x + v.y + v.z + v.w;
        }
        s_scan2[tid] = local;
        __syncthreads();
        for (int off = 1; off < G2T; off <<= 1) {
            unsigned t = (tid >= off) ? s_scan2[tid - off] : 0u;
            __syncthreads();
            s_scan2[tid] += t;
            __syncthreads();
        }
        const unsigned incl = s_scan2[tid];
        const unsigned excl = incl - local;
        if (jrem >= excl && jrem < incl) {
            unsigned acc = excl;
#pragma unroll
            for (int q = 0; q < 16; q++) {
                if (jrem < acc + cb_[q]) {
                    s_cb = (unsigned)(tid * 16 + q);
                    s_remc = jrem - acc;
                    break;
                }
                acc += cb_[q];
            }
        }
        __syncthreads();
    }
    const unsigned cb = s_cb;
    const unsigned remc = s_remc;
    __syncthreads();

    // ---- level 2: 256 fine bins of coarse bucket cb ----
    {
        unsigned local = fine[cb * 256u + (unsigned)tid];
        s_scan2[tid] = local;
        __syncthreads();
        for (int off = 1; off < G2T; off <<= 1) {
            unsigned t = (tid >= off) ? s_scan2[tid - off] : 0u;
            __syncthreads();
            s_scan2[tid] += t;
            __syncthreads();
        }
        const unsigned incl = s_scan2[tid];
        const unsigned excl = incl - local;
        if (remc >= excl && remc < incl) {
            g_state[m].T32 = L + cb * 256u + (unsigned)tid;
            g_state[m].r = remc - excl;
        }
    }
    if (threadIdx.x == 0) {
        g_below[m] = 0;  // reset for next replay
        g_done2[m] = 0;
    }
}

// ---------------------------------------------------------------------------
// K3: mask write (strict >) + tie collection + hist zeroing + fused tie fix
// ---------------------------------------------------------------------------
__global__ __launch_bounds__(GMT) void mask_kernel(
    const float4* __restrict__ A, const float4* __restrict__ B,
    float4* __restrict__ out, int n4) {
    const int m = blockIdx.y;
    const float4* src = m ? B : A;
    float4* dst = out + (size_t)m * (size_t)n4;
    const unsigned T = g_state[m].T32;

    const int stride = GMT * gridDim.x;
    for (int i = blockIdx.x * GMT + threadIdx.x; i < n4; i += stride) {
        float4 v = __ldg(src + i);
        unsigned bx = __float_as_uint(v.x) & ABS_MASK;
        unsigned by = __float_as_uint(v.y) & ABS_MASK;
        unsigned bz = __float_as_uint(v.z) & ABS_MASK;
        unsigned bw = __float_as_uint(v.w) & ABS_MASK;
        float4 o;
        o.x = (bx > T) ? 1.0f : 0.0f;
        o.y = (by > T) ? 1.0f : 0.0f;
        o.z = (bz > T) ? 1.0f : 0.0f;
        o.w = (bw > T) ? 1.0f : 0.0f;
        dst[i] = o;
        // exact-equality ties are extremely sparse (~1-16 per matrix)
        if (bx == T || by == T || bz == T || bw == T) {
            const unsigned idx = 4u * (unsigned)i;
            if (bx == T) {
                unsigned p = atomicAdd(&g_tie_cnt[m], 1u);
                if (p < TIE_CAP) g_tie_idx[m][p] = idx + 0u;
            }
            if (by == T) {
                unsigned p = atomicAdd(&g_tie_cnt[m], 1u);
                if (p < TIE_CAP) g_tie_idx[m][p] = idx + 1u;
            }
            if (bz == T) {
                unsigned p = atomicAdd(&g_tie_cnt[m], 1u);
                if (p < TIE_CAP) g_tie_idx[m][p] = idx + 2u;
            }
            if (bw == T) {
                unsigned p = atomicAdd(&g_tie_cnt[m], 1u);
                if (p < TIE_CAP) g_tie_idx[m][p] = idx + 3u;
            }
        }
    }

    // zero bracket histograms for the next graph replay
    {
        const int tid = ((int)blockIdx.y * (int)gridDim.x + (int)blockIdx.x) * GMT
                        + (int)threadIdx.x;
        const int tot = (int)gridDim.x * 2 * GMT;
        uint4 z4 = make_uint4(0u, 0u, 0u, 0u);
        uint4* f4 = (uint4*)&g_fine[0][0];
        for (int k = tid; k < 2 * FINE_BINS / 4; k += tot) f4[k] = z4;
        unsigned* cc = &g_crs[0][0];
        for (int k = tid; k < 2 * CRS_BINS; k += tot) cc[k] = 0;
    }

    // ---- last-block-done handshake, then in-place tie resolution ----
    __threadfence();
    __syncthreads();
    __shared__ unsigned s_isLast;
    if (threadIdx.x == 0)
        s_isLast = (atomicAdd(&g_done3[m], 1u) == gridDim.x - 1u) ? 1u : 0u;
    __syncthreads();
    if (!s_isLast) return;
    __threadfence();

    unsigned tc = g_tie_cnt[m];
    if (tc > TIE_CAP) tc = TIE_CAP;
    const unsigned r = g_state[m].r;
    float* dstf = (float*)(out) + (size_t)m * (size_t)n4 * 4u;
    for (unsigned e = threadIdx.x; e < tc; e += GMT) {
        const unsigned my = g_tie_idx[m][e];
        unsigned rk = 0;
        for (unsigned k = 0; k < tc; k++)
            rk += (g_tie_idx[m][k] < my) ? 1u : 0u;
        if (rk >= r) dstf[my] = 1.0f;
    }
    __syncthreads();
    if (threadIdx.x == 0) {
        g_tie_cnt[m] = 0;  // reset for next replay
        g_done3[m] = 0;
    }
}

// ---------------------------------------------------------------------------
extern "C" void kernel_launch(void* const* d_in, const int* in_sizes, int n_in,
                              void* d_out, int out_size) {
    const float4* A = (const float4*)d_in[0];
    const float4* B = (const float4*)d_in[1];
    float4* out = (float4*)d_out;

    const unsigned n = (unsigned)in_sizes[0];  // 16,777,216 per matrix
    const int n4 = (int)(n / 4u);
    // Mirror Python int((1.0 - 0.1) * n) exactly (double arithmetic, truncate)
    const unsigned j = (unsigned)((1.0 - 0.1) * (double)n);

    dim3 g1(G1X, 2);
    sample_kernel<<<g1, G1T>>>(A, B, n4, j);

    dim3 g2(G2X, 2);
    bracket_kernel<<<g2, G2T>>>(A, B, n4, j);

    dim3 gm(GMX, 2);
    mask_kernel<<<gm, GMT>>>(A, B, out, n4);
}